// round 17
// baseline (speedup 1.0000x reference)
#include <cuda_runtime.h>
#include <cuda_fp16.h>

// 4-qubit depth-2 variational circuit, B=2^20 samples. ONE persistent kernel.
//
// Per-block prologue (shuffle-based, ~2k cycles, no per-thread arrays):
// builds the batch-independent correction tensor T' (81 half2 wire-pairs)
// and the base info. Then grid-stride over sample tiles:
// z_w = base_w + fp16 Horner correction,
//   base_w = sign_w * prod_{q in mask_w} cos(x_q pi)  (exact weights->0 limit;
//   analytic pullback Z0->Z0Z1Z3, Z1->Z0Z2Z3, Z2->Z1Z3, Z3->Z0Z2 verified at
//   runtime, generic fallback otherwise),
//   corr_w = sum_{i0} r0 sum_{i1} r1 sum_{i2} r2 sum_{i3} r3 T'.
// 2 samples/thread on wire-pair half2 lanes. __launch_bounds__(256,4) caps
// regs at 64 (main loop needs 47) so 4 blocks/SM stay resident, no spills.

__device__ __forceinline__ __half2 u2h(unsigned v) {
    return *reinterpret_cast<__half2*>(&v);
}
__device__ __forceinline__ unsigned h2u(__half2 h) {
    return *reinterpret_cast<unsigned*>(&h);
}

// generic base: sign * prod over masked wires of C[q]
__device__ __forceinline__ float base_eval(int info, const float* C) {
    int code = info >> 4;
    float b = (code == 1) ? 1.0f : ((code == 2) ? -1.0f : 0.0f);
    b *= (info & 8) ? C[0] : 1.0f;
    b *= (info & 4) ? C[1] : 1.0f;
    b *= (info & 2) ? C[2] : 1.0f;
    b *= (info & 1) ? C[3] : 1.0f;
    return b;
}

__global__ void __launch_bounds__(256, 4) qc_kernel(
    const float4* __restrict__ x, const float* __restrict__ w,
    float4* __restrict__ out, int h /* B/2 */, int ntiles) {
    __shared__ float bufR[16][16], bufI[16][16];  // [state s][column j]
    __shared__ float sA[4][16][16];
    __shared__ float2 sTrig[16];
    __shared__ float4 sT[81];
    __shared__ uint2 Ts[81];   // half2 wire-pairs: .x=(w0,w1) .y=(w2,w3)
    __shared__ int sBI[4];
    __shared__ int sFast;
    const int tid = threadIdx.x;
    const unsigned FULL = 0xFFFFFFFFu;

    // ================= per-block prep (shuffle-based, register-lean) =================
    if (tid < 16) {
        float c, s;
        __sincosf(0.5f * w[tid], &s, &c);
        sTrig[tid] = make_float2(c, s);
    }
    // layout: column j = tid>>4, state s = tid&15 (pairs + perm stay in-warp)
    {
        const int j = tid >> 4;
        const int s = tid & 15;
        const int lane = tid & 31;
        float ar = (s == j) ? 1.0f : 0.0f;
        float ai = 0.0f;
        __syncthreads();

#pragma unroll
        for (int d = 0; d < 2; ++d) {
            int src = s;
            if (src & 1) src ^= 8;
            if (src & 2) src ^= 1;
            if (src & 4) src ^= 2;
            if (src & 8) src ^= 4;
            {
                float nar = __shfl_sync(FULL, ar, (lane & 16) | src);
                float nai = __shfl_sync(FULL, ai, (lane & 16) | src);
                ar = nar; ai = nai;
            }
#pragma unroll
            for (int q = 0; q < 4; ++q) {
                const int m = 8 >> q;
                float2 ty = sTrig[d * 8 + q * 2 + 0];
                float2 tz = sTrig[d * 8 + q * 2 + 1];
                float pr = __shfl_xor_sync(FULL, ar, m);
                float pi = __shfl_xor_sync(FULL, ai, m);
                float cy = ty.x, sy = ty.y, cp = tz.x, sp = tz.y;
                float nr, ni;
                if (s & m) { nr = cy * ar + sy * pr;  ni = cy * ai + sy * pi; }
                else       { nr = cy * ar - sy * pr;  ni = cy * ai - sy * pi; }
                if (s & m) { ar = nr * cp - ni * sp;  ai = ni * cp + nr * sp; }
                else       { ar = nr * cp + ni * sp;  ai = ni * cp - nr * sp; }
            }
        }
        bufR[s][j] = ar; bufI[s][j] = ai;
    }
    __syncthreads();

    // A_w[jj][jp] = sum_s sign_w(s)*(Ur[s][jj]Ur[s][jp]+Ui[s][jj]Ui[s][jp])
#pragma unroll 1
    for (int e = tid; e < 1024; e += 256) {
        int wq = e >> 8;
        int jj = (e >> 4) & 15;
        int jp = e & 15;
        int mask = 8 >> wq;
        float acc = 0.f;
#pragma unroll
        for (int ss = 0; ss < 16; ++ss) {
            float v = bufR[ss][jj] * bufR[ss][jp] + bufI[ss][jj] * bufI[ss][jp];
            acc += (ss & mask) ? -v : v;
        }
        sA[wq][jj][jp] = acc;
    }
    __syncthreads();

    // sparse basis change A -> T (16 nonzero (j,jp) pairs per (k,l))
    if (tid < 81) {
        int k = tid / 9, l = tid % 9;
        int i0 = k / 3, i1 = k % 3, i2 = l / 3, i3 = l % 3;
        int x0 = (i0 == 2), x1 = (i1 == 2), x2 = (i2 == 2), x3 = (i3 == 2);
        int n0 = (i0 == 1), n1 = (i1 == 1), n2 = (i2 == 1), n3 = (i3 == 1);
        float t4[4] = {0.f, 0.f, 0.f, 0.f};
#pragma unroll 1
        for (int c = 0; c < 16; ++c) {
            int o0 = (c >> 3) & 1, o1 = (c >> 2) & 1, o2 = (c >> 1) & 1, o3 = c & 1;
            int jj = (o0 << 3) | (o1 << 2) | (o2 << 1) | o3;
            int jp = ((o0 ^ x0) << 3) | ((o1 ^ x1) << 2) | ((o2 ^ x2) << 1) | (o3 ^ x3);
            int neg = (n0 & o0) ^ (n1 & o1) ^ (n2 & o2) ^ (n3 & o3);
            float sgn = neg ? -1.0f : 1.0f;
#pragma unroll
            for (int wq = 0; wq < 4; ++wq) t4[wq] += sgn * sA[wq][jj][jp];
        }
        const float inv16 = 1.0f / 16.0f;
        sT[tid] = make_float4(t4[0] * inv16, t4[1] * inv16,
                              t4[2] * inv16, t4[3] * inv16);
    }
    __syncthreads();

    // per wire: round pure-cos entries (all indices in {0,1}) to integers;
    // record dominant (mask, sign), subtract in place.
    if (tid < 4) {
        const int wq = tid;
        int info = 0;
#pragma unroll 1
        for (int c = 0; c < 16; ++c) {
            int b0 = (c >> 3) & 1, b1 = (c >> 2) & 1, b2 = (c >> 1) & 1, b3 = c & 1;
            int kl = 27 * b0 + 9 * b1 + 3 * b2 + b3;
            float* p = &((float*)&sT[kl])[wq];
            float v = *p;
            float r = rintf(v);
            if (r != 0.0f) {
                *p = v - r;
                info = c | ((r > 0.0f ? 1 : 2) << 4);
            }
        }
        sBI[wq] = info;
    }
    __syncthreads();

    if (tid == 0) {
        // analytic expectation: masks 13/11/5/10, all sign=+1 (code 1)
        sFast = (sBI[0] == (13 | 16) && sBI[1] == (11 | 16) &&
                 sBI[2] == (5 | 16)  && sBI[3] == (10 | 16)) ? 1 : 0;
    }
    if (tid < 81) {
        float4 f = sT[tid];
        __half2 h01 = make_half2(__float2half_rn(f.x), __float2half_rn(f.y));
        __half2 h23 = make_half2(__float2half_rn(f.z), __float2half_rn(f.w));
        uint2 p; p.x = h2u(h01); p.y = h2u(h23);
        Ts[tid] = p;
    }
    __syncthreads();

    // ================= persistent main loop: grid-stride tiles =================
    const float PI_F = 3.14159265358979323846f;
    const int fast = sFast;
    for (int tile = blockIdx.x; tile < ntiles; tile += gridDim.x) {
        int t = tile * 256 + tid;
        if (t >= h) continue;

        float4 xa = x[t];
        float4 xb = x[t + h];

        float Cf[2][4], Sf[2][4];
        __sincosf(xa.x * PI_F, &Sf[0][0], &Cf[0][0]);
        __sincosf(xa.y * PI_F, &Sf[0][1], &Cf[0][1]);
        __sincosf(xa.z * PI_F, &Sf[0][2], &Cf[0][2]);
        __sincosf(xa.w * PI_F, &Sf[0][3], &Cf[0][3]);
        __sincosf(xb.x * PI_F, &Sf[1][0], &Cf[1][0]);
        __sincosf(xb.y * PI_F, &Sf[1][1], &Cf[1][1]);
        __sincosf(xb.z * PI_F, &Sf[1][2], &Cf[1][2]);
        __sincosf(xb.w * PI_F, &Sf[1][3], &Cf[1][3]);

        float base[2][4];
        if (fast) {
#pragma unroll
            for (int smp = 0; smp < 2; ++smp) {
                float p03 = Cf[smp][0] * Cf[smp][3];
                base[smp][0] = p03 * Cf[smp][1];          // Z0 -> C0 C1 C3
                base[smp][1] = p03 * Cf[smp][2];          // Z1 -> C0 C2 C3
                base[smp][2] = Cf[smp][1] * Cf[smp][3];   // Z2 -> C1 C3
                base[smp][3] = Cf[smp][0] * Cf[smp][2];   // Z3 -> C0 C2
            }
        } else {
            int b0 = sBI[0], b1 = sBI[1], b2 = sBI[2], b3 = sBI[3];
#pragma unroll
            for (int smp = 0; smp < 2; ++smp) {
                base[smp][0] = base_eval(b0, Cf[smp]);
                base[smp][1] = base_eval(b1, Cf[smp]);
                base[smp][2] = base_eval(b2, Cf[smp]);
                base[smp][3] = base_eval(b3, Cf[smp]);
            }
        }

        __half2 CA[4], SA[4], CB[4], SB[4];
#pragma unroll
        for (int qb = 0; qb < 4; ++qb) {
            CA[qb] = __float2half2_rn(Cf[0][qb]);
            SA[qb] = __float2half2_rn(Sf[0][qb]);
            CB[qb] = __float2half2_rn(Cf[1][qb]);
            SB[qb] = __float2half2_rn(Sf[1][qb]);
        }

        __half2 zA0, zA1, zB0, zB1;

#pragma unroll
        for (int i0 = 0; i0 < 3; ++i0) {
            __half2 tA0, tA1, tB0, tB1;
#pragma unroll
            for (int i1 = 0; i1 < 3; ++i1) {
                const int gbase = (i0 * 3 + i1) * 9;
                __half2 uA0, uA1, uB0, uB1;
#pragma unroll
                for (int i2 = 0; i2 < 3; ++i2) {
                    uint2 a = Ts[gbase + i2 * 3 + 0];
                    uint2 b = Ts[gbase + i2 * 3 + 1];
                    uint2 c = Ts[gbase + i2 * 3 + 2];
                    __half2 Ta0 = u2h(a.x), Ta1 = u2h(a.y);
                    __half2 Tb0 = u2h(b.x), Tb1 = u2h(b.y);
                    __half2 Tc0 = u2h(c.x), Tc1 = u2h(c.y);
                    __half2 vA0 = __hfma2(CA[3], Tb0, Ta0);
                    __half2 vA1 = __hfma2(CA[3], Tb1, Ta1);
                    __half2 vB0 = __hfma2(CB[3], Tb0, Ta0);
                    __half2 vB1 = __hfma2(CB[3], Tb1, Ta1);
                    vA0 = __hfma2(SA[3], Tc0, vA0);
                    vA1 = __hfma2(SA[3], Tc1, vA1);
                    vB0 = __hfma2(SB[3], Tc0, vB0);
                    vB1 = __hfma2(SB[3], Tc1, vB1);
                    if (i2 == 0) { uA0 = vA0; uA1 = vA1; uB0 = vB0; uB1 = vB1; }
                    else if (i2 == 1) {
                        uA0 = __hfma2(CA[2], vA0, uA0);
                        uA1 = __hfma2(CA[2], vA1, uA1);
                        uB0 = __hfma2(CB[2], vB0, uB0);
                        uB1 = __hfma2(CB[2], vB1, uB1);
                    } else {
                        uA0 = __hfma2(SA[2], vA0, uA0);
                        uA1 = __hfma2(SA[2], vA1, uA1);
                        uB0 = __hfma2(SB[2], vB0, uB0);
                        uB1 = __hfma2(SB[2], vB1, uB1);
                    }
                }
                if (i1 == 0) { tA0 = uA0; tA1 = uA1; tB0 = uB0; tB1 = uB1; }
                else if (i1 == 1) {
                    tA0 = __hfma2(CA[1], uA0, tA0);
                    tA1 = __hfma2(CA[1], uA1, tA1);
                    tB0 = __hfma2(CB[1], uB0, tB0);
                    tB1 = __hfma2(CB[1], uB1, tB1);
                } else {
                    tA0 = __hfma2(SA[1], uA0, tA0);
                    tA1 = __hfma2(SA[1], uA1, tA1);
                    tB0 = __hfma2(SB[1], uB0, tB0);
                    tB1 = __hfma2(SB[1], uB1, tB1);
                }
            }
            if (i0 == 0) { zA0 = tA0; zA1 = tA1; zB0 = tB0; zB1 = tB1; }
            else if (i0 == 1) {
                zA0 = __hfma2(CA[0], tA0, zA0);
                zA1 = __hfma2(CA[0], tA1, zA1);
                zB0 = __hfma2(CB[0], tB0, zB0);
                zB1 = __hfma2(CB[0], tB1, zB1);
            } else {
                zA0 = __hfma2(SA[0], tA0, zA0);
                zA1 = __hfma2(SA[0], tA1, zA1);
                zB0 = __hfma2(SB[0], tB0, zB0);
                zB1 = __hfma2(SB[0], tB1, zB1);
            }
        }

        out[t] = make_float4(base[0][0] + __low2float(zA0),
                             base[0][1] + __high2float(zA0),
                             base[0][2] + __low2float(zA1),
                             base[0][3] + __high2float(zA1));
        out[t + h] = make_float4(base[1][0] + __low2float(zB0),
                                 base[1][1] + __high2float(zB0),
                                 base[1][2] + __low2float(zB1),
                                 base[1][3] + __high2float(zB1));
    }
}

extern "C" void kernel_launch(void* const* d_in, const int* in_sizes, int n_in,
                              void* d_out, int out_size) {
    const float* x = (const float*)d_in[0];       // [B,4]
    const float* w = (const float*)d_in[1];       // [2,4,2]
    float* out = (float*)d_out;                   // [B,4]
    int B = in_sizes[0] / 4;
    int h = B / 2;
    int ntiles = (h + 255) / 256;

    int sms = 148;
    cudaDeviceGetAttribute(&sms, cudaDevAttrMultiProcessorCount, 0);
    int blocks = 4 * sms;                 // 4 resident blocks/SM (regs capped 64)
    if (blocks > ntiles) blocks = ntiles;

    qc_kernel<<<blocks, 256>>>((const float4*)x, w, (float4*)out, h, ntiles);
}